// round 7
// baseline (speedup 1.0000x reference)
#include <cuda_runtime.h>
#include <cuda_bf16.h>
#include <cstdint>

// Problem constants
#define B_      32
#define NHEAD   32
#define NKV     8
#define NREP    4
#define HDIM    128
#define HIDDEN_ 4096
#define QKV_OUT_ 6144          // (8*2+32)*128
#define QD      4096           // NHEAD*HDIM
#define KD      1024           // NKV*HDIM
#define PAST    2048
#define T_TOT   2049           // PAST + 1
#define SCALE_  0.08838834764831845f  // 1/sqrt(128)

// d_out layout: [out (32*32*128)] [k_cat (32*2049*8*128)] [v_cat (...)]
#define OFF_OUT 0
#define SZ_OUT  (B_*NHEAD*HDIM)
#define OFF_K   (SZ_OUT)
#define SZ_KC   ((size_t)B_*T_TOT*NKV*HDIM)
#define OFF_V   (OFF_K + SZ_KC)

// GEMM split-K
#define KSPLIT  8
#define KPER    (HIDDEN_/KSPLIT)                // 512
#define KCH     32
#define NTILE   128
#define XSTR    40                               // smem row stride in bf16 (80B, 16B-aligned, conflict-free ldmatrix)

// attention chunking
#define TCHUNK  256
#define NCHUNK  9

// ---------------- scratch ----------------
__device__ float g_part[KSPLIT * B_ * QKV_OUT_];
__device__ float g_q[B_ * QD];
__device__ float g_pm[B_ * NKV * NCHUNK * NREP];
__device__ float g_pl[B_ * NKV * NCHUNK * NREP];
__device__ float g_pacc[B_ * NKV * NCHUNK * NREP * HDIM];

// ---------------- tensor-core helpers ----------------
__device__ __forceinline__ uint32_t smem_u32(const void* p) {
    return (uint32_t)__cvta_generic_to_shared(p);
}

__device__ __forceinline__ void ldsm4(uint32_t* r, uint32_t addr) {
    asm volatile("ldmatrix.sync.aligned.m8n8.x4.shared.b16 {%0,%1,%2,%3}, [%4];\n"
                 : "=r"(r[0]), "=r"(r[1]), "=r"(r[2]), "=r"(r[3]) : "r"(addr));
}

__device__ __forceinline__ void mma_bf16(float* d, const uint32_t* a, const uint32_t* b) {
    asm volatile(
        "mma.sync.aligned.m16n8k16.row.col.f32.bf16.bf16.f32 "
        "{%0,%1,%2,%3}, {%4,%5,%6,%7}, {%8,%9}, {%0,%1,%2,%3};\n"
        : "+f"(d[0]), "+f"(d[1]), "+f"(d[2]), "+f"(d[3])
        : "r"(a[0]), "r"(a[1]), "r"(a[2]), "r"(a[3]), "r"(b[0]), "r"(b[1]));
}

__device__ __forceinline__ void cvt_hilo(float x, __nv_bfloat16& h, __nv_bfloat16& l) {
    h = __float2bfloat16(x);
    l = __float2bfloat16(x - __bfloat162float(h));
}

// ---------------- Kernel 1: QKV GEMM via bf16 hi/lo split on tensor cores ----------------
// C[32, 6144] partial over K-slice. Block: 32(M) x 128(N), 256 threads (8 warps).
// Warp w: wm = w&1 (m16 tile), wn = w>>1 (n32 tile).
__global__ __launch_bounds__(256) void gemm_kernel(
    const float* __restrict__ X, const float* __restrict__ W)
{
    __shared__ __nv_bfloat16 Xh[32][XSTR], Xl[32][XSTR];
    __shared__ __nv_bfloat16 Wh[NTILE][XSTR], Wl[NTILE][XSTR];

    const int tid = threadIdx.x;
    const int warp = tid >> 5, lane = tid & 31;
    const int wm = warp & 1, wn = warp >> 1;
    const int o0 = blockIdx.x * NTILE;
    const int k0 = blockIdx.y * KPER;

    float d[4][4];
#pragma unroll
    for (int i = 0; i < 4; i++)
#pragma unroll
        for (int j = 0; j < 4; j++) d[i][j] = 0.f;

    // ldmatrix source addresses (constant across the k-loop except the kk offset)
    const int a_row = wm * 16 + (lane & 7) + ((lane & 8) ? 8 : 0);
    const int a_ks  = (lane & 16) ? 8 : 0;
    const int b_row0 = wn * 32 + (lane & 7) + ((lane & 16) ? 8 : 0);
    const int b_ks  = (lane & 8) ? 8 : 0;

    for (int kc = 0; kc < KPER; kc += KCH) {
        // --- load + convert X tile: 32 rows x 32 k (256 float4, 1/thread) ---
        {
            int r = tid >> 3, c4 = (tid & 7) * 4;
            float4 v = *(const float4*)&X[(size_t)r * HIDDEN_ + k0 + kc + c4];
            cvt_hilo(v.x, Xh[r][c4+0], Xl[r][c4+0]);
            cvt_hilo(v.y, Xh[r][c4+1], Xl[r][c4+1]);
            cvt_hilo(v.z, Xh[r][c4+2], Xl[r][c4+2]);
            cvt_hilo(v.w, Xh[r][c4+3], Xl[r][c4+3]);
        }
        // --- load + convert W tile: 128 o x 32 k (1024 float4, 4/thread) ---
        {
            int o = tid >> 1;
            int base = (tid & 1) * 16;
            const float4* src = (const float4*)&W[(size_t)(o0 + o) * HIDDEN_ + k0 + kc + base];
#pragma unroll
            for (int i = 0; i < 4; i++) {
                float4 v = src[i];
                int kk = base + i * 4;
                cvt_hilo(v.x, Wh[o][kk+0], Wl[o][kk+0]);
                cvt_hilo(v.y, Wh[o][kk+1], Wl[o][kk+1]);
                cvt_hilo(v.z, Wh[o][kk+2], Wl[o][kk+2]);
                cvt_hilo(v.w, Wh[o][kk+3], Wl[o][kk+3]);
            }
        }
        __syncthreads();

#pragma unroll
        for (int ks = 0; ks < 2; ks++) {
            const int kk = ks * 16;
            uint32_t ah[4], al[4];
            ldsm4(ah, smem_u32(&Xh[a_row][kk + a_ks]));
            ldsm4(al, smem_u32(&Xl[a_row][kk + a_ks]));
            // B fragments: two ldmatrix.x4 per plane cover n32
            uint32_t bh[8], bl[8];
            ldsm4(bh + 0, smem_u32(&Wh[b_row0][kk + b_ks]));
            ldsm4(bh + 4, smem_u32(&Wh[b_row0 + 16][kk + b_ks]));
            ldsm4(bl + 0, smem_u32(&Wl[b_row0][kk + b_ks]));
            ldsm4(bl + 4, smem_u32(&Wl[b_row0 + 16][kk + b_ks]));
#pragma unroll
            for (int nt = 0; nt < 4; nt++) {
                uint32_t* Bh = bh + nt * 2;
                uint32_t* Bl = bl + nt * 2;
                mma_bf16(d[nt], ah, Bh);   // hi*hi
                mma_bf16(d[nt], ah, Bl);   // hi*lo
                mma_bf16(d[nt], al, Bh);   // lo*hi
            }
        }
        __syncthreads();
    }

    // --- store partials: frag c0,c1 -> (row g, col 2t..), c2,c3 -> (row g+8) ---
    const int g = lane >> 2, t2 = (lane & 3) * 2;
    const int ksb = blockIdx.y * B_;
#pragma unroll
    for (int nt = 0; nt < 4; nt++) {
        int o = o0 + wn * 32 + nt * 8 + t2;
        int b0 = wm * 16 + g;
        float* dst0 = &g_part[(size_t)(ksb + b0) * QKV_OUT_ + o];
        dst0[0] = d[nt][0]; dst0[1] = d[nt][1];
        float* dst1 = &g_part[(size_t)(ksb + b0 + 8) * QKV_OUT_ + o];
        dst1[0] = d[nt][2]; dst1[1] = d[nt][3];
    }
}

// ---------------- Kernel 2: split-K reduce + bias + scatter ----------------
__global__ __launch_bounds__(256) void gemm_reduce_kernel(
    const float* __restrict__ bias, float* __restrict__ out)
{
    int i = blockIdx.x * 256 + threadIdx.x;
    if (i >= B_ * QKV_OUT_) return;
    int b = i / QKV_OUT_, o = i - b * QKV_OUT_;
    float s = bias[o];
#pragma unroll
    for (int ks = 0; ks < KSPLIT; ks++)
        s += g_part[(size_t)(ks * B_ + b) * QKV_OUT_ + o];
    if (o < QD) {
        g_q[b * QD + o] = s;
    } else if (o < QD + KD) {
        int r = o - QD;
        out[OFF_K + ((size_t)b * T_TOT + PAST) * KD + r] = s;
    } else {
        int r = o - QD - KD;
        out[OFF_V + ((size_t)b * T_TOT + PAST) * KD + r] = s;
    }
}

// ---------------- Kernel 3: fused cache-copy + split-KV flash attention ----------------
__global__ __launch_bounds__(256) void attn_kernel(
    const float* __restrict__ Kc, const float* __restrict__ Vc,
    const float* __restrict__ mask, float* __restrict__ out)
{
    const int ch = blockIdx.x, kv = blockIdx.y, b = blockIdx.z;
    const int w = threadIdx.x >> 5, lane = threadIdx.x & 31;

    float4 q[NREP];
#pragma unroll
    for (int h = 0; h < NREP; h++)
        q[h] = *(const float4*)&g_q[(size_t)b * QD + (kv * NREP + h) * HDIM + lane * 4];

    float m[NREP], l[NREP];
    float4 acc[NREP];
#pragma unroll
    for (int h = 0; h < NREP; h++) {
        m[h] = -1e30f; l[h] = 0.f;
        acc[h] = make_float4(0.f, 0.f, 0.f, 0.f);
    }

    const int t0 = ch * TCHUNK + w * 32;
    for (int j = 0; j < 32; j++) {
        int t = t0 + j;
        if (t >= T_TOT) break;
        size_t dsti = (((size_t)b * T_TOT + t) * NKV + kv) * HDIM;
        float4 k4, v4;
        if (t < PAST) {
            size_t srci = (((size_t)b * PAST + t) * NKV + kv) * HDIM;
            k4 = ((const float4*)(Kc + srci))[lane];
            v4 = ((const float4*)(Vc + srci))[lane];
            ((float4*)(out + OFF_K + dsti))[lane] = k4;
            ((float4*)(out + OFF_V + dsti))[lane] = v4;
        } else {
            k4 = ((const float4*)(out + OFF_K + dsti))[lane];
            v4 = ((const float4*)(out + OFF_V + dsti))[lane];
        }
        float s[NREP];
#pragma unroll
        for (int h = 0; h < NREP; h++)
            s[h] = q[h].x * k4.x + q[h].y * k4.y + q[h].z * k4.z + q[h].w * k4.w;
#pragma unroll
        for (int off = 16; off; off >>= 1) {
#pragma unroll
            for (int h = 0; h < NREP; h++)
                s[h] += __shfl_xor_sync(0xFFFFFFFFu, s[h], off);
        }
        float mk = __ldg(&mask[(size_t)b * T_TOT + t]);
#pragma unroll
        for (int h = 0; h < NREP; h++) {
            float sv = s[h] * SCALE_ + mk;
            float mn = fmaxf(m[h], sv);
            float corr = __expf(m[h] - mn);
            float p = __expf(sv - mn);
            l[h] = l[h] * corr + p;
            acc[h].x = acc[h].x * corr + p * v4.x;
            acc[h].y = acc[h].y * corr + p * v4.y;
            acc[h].z = acc[h].z * corr + p * v4.z;
            acc[h].w = acc[h].w * corr + p * v4.w;
            m[h] = mn;
        }
    }

    __shared__ float sm_m[8][NREP];
    __shared__ float sm_l[8][NREP];
    __shared__ float sm_acc[8][NREP][HDIM];
    if (lane < NREP) { sm_m[w][lane] = m[lane]; sm_l[w][lane] = l[lane]; }
#pragma unroll
    for (int h = 0; h < NREP; h++)
        *(float4*)&sm_acc[w][h][lane * 4] = acc[h];
    __syncthreads();

    const int base = ((b * NKV + kv) * NCHUNK + ch) * NREP;
    for (int e = threadIdx.x; e < NREP * HDIM; e += 256) {
        int h = e >> 7, dd = e & 127;
        float M = sm_m[0][h];
#pragma unroll
        for (int ww = 1; ww < 8; ww++) M = fmaxf(M, sm_m[ww][h]);
        float a = 0.f;
#pragma unroll
        for (int ww = 0; ww < 8; ww++)
            a += sm_acc[ww][h][dd] * __expf(sm_m[ww][h] - M);
        g_pacc[(size_t)(base + h) * HDIM + dd] = a;
    }
    if (threadIdx.x < NREP) {
        int h = threadIdx.x;
        float M = sm_m[0][h];
#pragma unroll
        for (int ww = 1; ww < 8; ww++) M = fmaxf(M, sm_m[ww][h]);
        float L = 0.f;
#pragma unroll
        for (int ww = 0; ww < 8; ww++)
            L += sm_l[ww][h] * __expf(sm_m[ww][h] - M);
        g_pm[base + h] = M;
        g_pl[base + h] = L;
    }
}

// ---------------- Kernel 4: cross-chunk softmax reduce ----------------
__global__ __launch_bounds__(128) void attn_final_kernel(float* __restrict__ out)
{
    const int h = blockIdx.x, b = blockIdx.y, d = threadIdx.x;
    const int kv = h >> 2, hh = h & 3;
    const int base0 = (b * NKV + kv) * NCHUNK;
    float M = -1e30f;
#pragma unroll
    for (int ch = 0; ch < NCHUNK; ch++)
        M = fmaxf(M, g_pm[(base0 + ch) * NREP + hh]);
    float L = 0.f, A = 0.f;
#pragma unroll
    for (int ch = 0; ch < NCHUNK; ch++) {
        int idx = (base0 + ch) * NREP + hh;
        float f = __expf(g_pm[idx] - M);
        L += g_pl[idx] * f;
        A += g_pacc[(size_t)idx * HDIM + d] * f;
    }
    out[OFF_OUT + ((size_t)b * NHEAD + h) * HDIM + d] = A / L;
}

// ---------------- launch ----------------
extern "C" void kernel_launch(void* const* d_in, const int* in_sizes, int n_in,
                              void* d_out, int out_size)
{
    const float* input_t = (const float*)d_in[0];
    const float* key_cache = (const float*)d_in[1];
    const float* value_cache = (const float*)d_in[2];
    const float* attention_mask = (const float*)d_in[4];
    const float* W_qkv = (const float*)d_in[6];
    const float* b_qkv = (const float*)d_in[7];
    float* out = (float*)d_out;

    gemm_kernel<<<dim3(QKV_OUT_ / NTILE, KSPLIT), 256>>>(input_t, W_qkv);
    gemm_reduce_kernel<<<(B_ * QKV_OUT_ + 255) / 256, 256>>>(b_qkv, out);
    attn_kernel<<<dim3(NCHUNK, NKV, B_), 256>>>(key_cache, value_cache, attention_mask, out);
    attn_final_kernel<<<dim3(NHEAD, B_), 128>>>(out);
}

// round 12
// speedup vs baseline: 1.0813x; 1.0813x over previous
#include <cuda_runtime.h>
#include <cuda_bf16.h>
#include <cstdint>

// Problem constants
#define B_      32
#define NHEAD   32
#define NKV     8
#define NREP    4
#define HDIM    128
#define HIDDEN_ 4096
#define QKV_OUT_ 6144          // (8*2+32)*128
#define QD      4096           // NHEAD*HDIM
#define KD      1024           // NKV*HDIM
#define PAST    2048
#define T_TOT   2049           // PAST + 1
#define SCALE_  0.08838834764831845f  // 1/sqrt(128)

// d_out layout: [out (32*32*128)] [k_cat (32*2049*8*128)] [v_cat (...)]
#define OFF_OUT 0
#define SZ_OUT  (B_*NHEAD*HDIM)
#define OFF_K   (SZ_OUT)
#define SZ_KC   ((size_t)B_*T_TOT*NKV*HDIM)
#define OFF_V   (OFF_K + SZ_KC)

// GEMM split-K
#define KSPLIT  8
#define KPER    (HIDDEN_/KSPLIT)                // 512
#define KCH     32
#define NTILE   128
#define XSTR    40

// attention chunking
#define TCHUNK  256
#define NCHUNK  9

// ---------------- scratch ----------------
__device__ float g_part[KSPLIT * B_ * QKV_OUT_];
__device__ float g_q[B_ * QD];
__device__ float g_pm[B_ * NKV * NCHUNK * NREP];
__device__ float g_pl[B_ * NKV * NCHUNK * NREP];
__device__ float g_pacc[B_ * NKV * NCHUNK * NREP * HDIM];

// ---------------- tensor-core helpers ----------------
__device__ __forceinline__ uint32_t smem_u32(const void* p) {
    return (uint32_t)__cvta_generic_to_shared(p);
}

__device__ __forceinline__ void ldsm4(uint32_t* r, uint32_t addr) {
    asm volatile("ldmatrix.sync.aligned.m8n8.x4.shared.b16 {%0,%1,%2,%3}, [%4];\n"
                 : "=r"(r[0]), "=r"(r[1]), "=r"(r[2]), "=r"(r[3]) : "r"(addr));
}

__device__ __forceinline__ void mma_bf16(float* d, const uint32_t* a, const uint32_t* b) {
    asm volatile(
        "mma.sync.aligned.m16n8k16.row.col.f32.bf16.bf16.f32 "
        "{%0,%1,%2,%3}, {%4,%5,%6,%7}, {%8,%9}, {%0,%1,%2,%3};\n"
        : "+f"(d[0]), "+f"(d[1]), "+f"(d[2]), "+f"(d[3])
        : "r"(a[0]), "r"(a[1]), "r"(a[2]), "r"(a[3]), "r"(b[0]), "r"(b[1]));
}

__device__ __forceinline__ void cvt_hilo(float x, __nv_bfloat16& h, __nv_bfloat16& l) {
    h = __float2bfloat16(x);
    l = __float2bfloat16(x - __bfloat162float(h));
}

// ---------------- Kernel 1: QKV GEMM via bf16 hi/lo split on tensor cores ----------------
__global__ __launch_bounds__(256) void gemm_kernel(
    const float* __restrict__ X, const float* __restrict__ W)
{
    __shared__ __nv_bfloat16 Xh[32][XSTR], Xl[32][XSTR];
    __shared__ __nv_bfloat16 Wh[NTILE][XSTR], Wl[NTILE][XSTR];

    const int tid = threadIdx.x;
    const int warp = tid >> 5, lane = tid & 31;
    const int wm = warp & 1, wn = warp >> 1;
    const int o0 = blockIdx.x * NTILE;
    const int k0 = blockIdx.y * KPER;

    float d[4][4];
#pragma unroll
    for (int i = 0; i < 4; i++)
#pragma unroll
        for (int j = 0; j < 4; j++) d[i][j] = 0.f;

    const int a_row = wm * 16 + (lane & 7) + ((lane & 8) ? 8 : 0);
    const int a_ks  = (lane & 16) ? 8 : 0;
    const int b_row0 = wn * 32 + (lane & 7) + ((lane & 16) ? 8 : 0);
    const int b_ks  = (lane & 8) ? 8 : 0;

    for (int kc = 0; kc < KPER; kc += KCH) {
        {
            int r = tid >> 3, c4 = (tid & 7) * 4;
            float4 v = *(const float4*)&X[(size_t)r * HIDDEN_ + k0 + kc + c4];
            cvt_hilo(v.x, Xh[r][c4+0], Xl[r][c4+0]);
            cvt_hilo(v.y, Xh[r][c4+1], Xl[r][c4+1]);
            cvt_hilo(v.z, Xh[r][c4+2], Xl[r][c4+2]);
            cvt_hilo(v.w, Xh[r][c4+3], Xl[r][c4+3]);
        }
        {
            int o = tid >> 1;
            int base = (tid & 1) * 16;
            const float4* src = (const float4*)&W[(size_t)(o0 + o) * HIDDEN_ + k0 + kc + base];
#pragma unroll
            for (int i = 0; i < 4; i++) {
                float4 v = src[i];
                int kk = base + i * 4;
                cvt_hilo(v.x, Wh[o][kk+0], Wl[o][kk+0]);
                cvt_hilo(v.y, Wh[o][kk+1], Wl[o][kk+1]);
                cvt_hilo(v.z, Wh[o][kk+2], Wl[o][kk+2]);
                cvt_hilo(v.w, Wh[o][kk+3], Wl[o][kk+3]);
            }
        }
        __syncthreads();

#pragma unroll
        for (int ks = 0; ks < 2; ks++) {
            const int kk = ks * 16;
            uint32_t ah[4], al[4];
            ldsm4(ah, smem_u32(&Xh[a_row][kk + a_ks]));
            ldsm4(al, smem_u32(&Xl[a_row][kk + a_ks]));
            uint32_t bh[8], bl[8];
            ldsm4(bh + 0, smem_u32(&Wh[b_row0][kk + b_ks]));
            ldsm4(bh + 4, smem_u32(&Wh[b_row0 + 16][kk + b_ks]));
            ldsm4(bl + 0, smem_u32(&Wl[b_row0][kk + b_ks]));
            ldsm4(bl + 4, smem_u32(&Wl[b_row0 + 16][kk + b_ks]));
#pragma unroll
            for (int nt = 0; nt < 4; nt++) {
                uint32_t* Bh = bh + nt * 2;
                uint32_t* Bl = bl + nt * 2;
                mma_bf16(d[nt], ah, Bh);
                mma_bf16(d[nt], ah, Bl);
                mma_bf16(d[nt], al, Bh);
            }
        }
        __syncthreads();
    }

    const int g = lane >> 2, t2 = (lane & 3) * 2;
    const int ksb = blockIdx.y * B_;
#pragma unroll
    for (int nt = 0; nt < 4; nt++) {
        int o = o0 + wn * 32 + nt * 8 + t2;
        int b0 = wm * 16 + g;
        float* dst0 = &g_part[(size_t)(ksb + b0) * QKV_OUT_ + o];
        dst0[0] = d[nt][0]; dst0[1] = d[nt][1];
        float* dst1 = &g_part[(size_t)(ksb + b0 + 8) * QKV_OUT_ + o];
        dst1[0] = d[nt][2]; dst1[1] = d[nt][3];
    }
}

// ---------------- Kernel 2: split-K reduce + bias + scatter ----------------
__global__ __launch_bounds__(256) void gemm_reduce_kernel(
    const float* __restrict__ bias, float* __restrict__ out)
{
    int i = blockIdx.x * 256 + threadIdx.x;
    if (i >= B_ * QKV_OUT_) return;
    int b = i / QKV_OUT_, o = i - b * QKV_OUT_;
    float s = bias[o];
#pragma unroll
    for (int ks = 0; ks < KSPLIT; ks++)
        s += g_part[(size_t)(ks * B_ + b) * QKV_OUT_ + o];
    if (o < QD) {
        g_q[b * QD + o] = s;
    } else if (o < QD + KD) {
        int r = o - QD;
        out[OFF_K + ((size_t)b * T_TOT + PAST) * KD + r] = s;
    } else {
        int r = o - QD - KD;
        out[OFF_V + ((size_t)b * T_TOT + PAST) * KD + r] = s;
    }
}

// ---------------- Kernel 3: fused cache-copy + split-KV flash attention ----------------
// 2 tokens per iteration: MLP=4 on the streamed loads, one softmax-corr per pair.
// __ldcs/__stcs: K/V touched exactly once -> keep it out of L2's working set.
__global__ __launch_bounds__(256) void attn_kernel(
    const float* __restrict__ Kc, const float* __restrict__ Vc,
    const float* __restrict__ mask, float* __restrict__ out)
{
    const int ch = blockIdx.x, kv = blockIdx.y, b = blockIdx.z;
    const int w = threadIdx.x >> 5, lane = threadIdx.x & 31;

    float4 q[NREP];
#pragma unroll
    for (int h = 0; h < NREP; h++)
        q[h] = *(const float4*)&g_q[(size_t)b * QD + (kv * NREP + h) * HDIM + lane * 4];

    float m[NREP], l[NREP];
    float4 acc[NREP];
#pragma unroll
    for (int h = 0; h < NREP; h++) {
        m[h] = -1e30f; l[h] = 0.f;
        acc[h] = make_float4(0.f, 0.f, 0.f, 0.f);
    }

    const int t0 = ch * TCHUNK + w * 32;
#pragma unroll 1
    for (int j = 0; j < 32; j += 2) {
        const int ta = t0 + j;
        if (ta >= T_TOT) break;
        const int tb = ta + 1;
        const bool bok = (tb < T_TOT);

        const size_t da = (((size_t)b * T_TOT + ta) * NKV + kv) * HDIM;
        const size_t db = da + (size_t)NKV * HDIM;

        float4 kA, vA, kB, vB;
        // ---- issue all 4 loads up front (MLP=4) ----
        if (ta < PAST) {
            size_t sa = (((size_t)b * PAST + ta) * NKV + kv) * HDIM;
            kA = __ldcs(((const float4*)(Kc + sa)) + lane);
            vA = __ldcs(((const float4*)(Vc + sa)) + lane);
        } else {
            kA = __ldg(((const float4*)(out + OFF_K + da)) + lane);
            vA = __ldg(((const float4*)(out + OFF_V + da)) + lane);
        }
        if (bok) {
            if (tb < PAST) {
                size_t sb = (((size_t)b * PAST + tb) * NKV + kv) * HDIM;
                kB = __ldcs(((const float4*)(Kc + sb)) + lane);
                vB = __ldcs(((const float4*)(Vc + sb)) + lane);
            } else {
                kB = __ldg(((const float4*)(out + OFF_K + db)) + lane);
                vB = __ldg(((const float4*)(out + OFF_V + db)) + lane);
            }
        } else {
            kB = make_float4(0.f, 0.f, 0.f, 0.f);
            vB = make_float4(0.f, 0.f, 0.f, 0.f);
        }
        float mka = __ldg(&mask[(size_t)b * T_TOT + ta]);
        float mkb = bok ? __ldg(&mask[(size_t)b * T_TOT + tb]) : 0.f;

        // ---- fused cache copy (streaming stores) ----
        if (ta < PAST) {
            __stcs(((float4*)(out + OFF_K + da)) + lane, kA);
            __stcs(((float4*)(out + OFF_V + da)) + lane, vA);
        }
        if (bok && tb < PAST) {
            __stcs(((float4*)(out + OFF_K + db)) + lane, kB);
            __stcs(((float4*)(out + OFF_V + db)) + lane, vB);
        }

        // ---- scores ----
        float sA[NREP], sB[NREP];
#pragma unroll
        for (int h = 0; h < NREP; h++) {
            sA[h] = q[h].x * kA.x + q[h].y * kA.y + q[h].z * kA.z + q[h].w * kA.w;
            sB[h] = q[h].x * kB.x + q[h].y * kB.y + q[h].z * kB.z + q[h].w * kB.w;
        }
#pragma unroll
        for (int off = 16; off; off >>= 1) {
#pragma unroll
            for (int h = 0; h < NREP; h++) {
                sA[h] += __shfl_xor_sync(0xFFFFFFFFu, sA[h], off);
                sB[h] += __shfl_xor_sync(0xFFFFFFFFu, sB[h], off);
            }
        }

        // ---- combined 2-token online-softmax update ----
#pragma unroll
        for (int h = 0; h < NREP; h++) {
            float svA = sA[h] * SCALE_ + mka;
            float svB = bok ? (sB[h] * SCALE_ + mkb) : -1e30f;
            float mn = fmaxf(m[h], fmaxf(svA, svB));
            float corr = __expf(m[h] - mn);
            float pA = __expf(svA - mn);
            float pB = __expf(svB - mn);
            l[h] = l[h] * corr + pA + pB;
            acc[h].x = acc[h].x * corr + pA * vA.x + pB * vB.x;
            acc[h].y = acc[h].y * corr + pA * vA.y + pB * vB.y;
            acc[h].z = acc[h].z * corr + pA * vA.z + pB * vB.z;
            acc[h].w = acc[h].w * corr + pA * vA.w + pB * vB.w;
            m[h] = mn;
        }
    }

    __shared__ float sm_m[8][NREP];
    __shared__ float sm_l[8][NREP];
    __shared__ float sm_acc[8][NREP][HDIM];
    if (lane < NREP) { sm_m[w][lane] = m[lane]; sm_l[w][lane] = l[lane]; }
#pragma unroll
    for (int h = 0; h < NREP; h++)
        *(float4*)&sm_acc[w][h][lane * 4] = acc[h];
    __syncthreads();

    const int base = ((b * NKV + kv) * NCHUNK + ch) * NREP;
    for (int e = threadIdx.x; e < NREP * HDIM; e += 256) {
        int h = e >> 7, dd = e & 127;
        float M = sm_m[0][h];
#pragma unroll
        for (int ww = 1; ww < 8; ww++) M = fmaxf(M, sm_m[ww][h]);
        float a = 0.f;
#pragma unroll
        for (int ww = 0; ww < 8; ww++)
            a += sm_acc[ww][h][dd] * __expf(sm_m[ww][h] - M);
        g_pacc[(size_t)(base + h) * HDIM + dd] = a;
    }
    if (threadIdx.x < NREP) {
        int h = threadIdx.x;
        float M = sm_m[0][h];
#pragma unroll
        for (int ww = 1; ww < 8; ww++) M = fmaxf(M, sm_m[ww][h]);
        float L = 0.f;
#pragma unroll
        for (int ww = 0; ww < 8; ww++)
            L += sm_l[ww][h] * __expf(sm_m[ww][h] - M);
        g_pm[base + h] = M;
        g_pl[base + h] = L;
    }
}

// ---------------- Kernel 4: cross-chunk softmax reduce ----------------
__global__ __launch_bounds__(128) void attn_final_kernel(float* __restrict__ out)
{
    const int h = blockIdx.x, b = blockIdx.y, d = threadIdx.x;
    const int kv = h >> 2, hh = h & 3;
    const int base0 = (b * NKV + kv) * NCHUNK;
    float M = -1e30f;
#pragma unroll
    for (int ch = 0; ch < NCHUNK; ch++)
        M = fmaxf(M, g_pm[(base0 + ch) * NREP + hh]);
    float L = 0.f, A = 0.f;
#pragma unroll
    for (int ch = 0; ch < NCHUNK; ch++) {
        int idx = (base0 + ch) * NREP + hh;
        float f = __expf(g_pm[idx] - M);
        L += g_pl[idx] * f;
        A += g_pacc[(size_t)idx * HDIM + d] * f;
    }
    out[OFF_OUT + ((size_t)b * NHEAD + h) * HDIM + d] = A / L;
}

// ---------------- launch ----------------
extern "C" void kernel_launch(void* const* d_in, const int* in_sizes, int n_in,
                              void* d_out, int out_size)
{
    const float* input_t = (const float*)d_in[0];
    const float* key_cache = (const float*)d_in[1];
    const float* value_cache = (const float*)d_in[2];
    const float* attention_mask = (const float*)d_in[4];
    const float* W_qkv = (const float*)d_in[6];
    const float* b_qkv = (const float*)d_in[7];
    float* out = (float*)d_out;

    gemm_kernel<<<dim3(QKV_OUT_ / NTILE, KSPLIT), 256>>>(input_t, W_qkv);
    gemm_reduce_kernel<<<(B_ * QKV_OUT_ + 255) / 256, 256>>>(b_qkv, out);
    attn_kernel<<<dim3(NCHUNK, NKV, B_), 256>>>(key_cache, value_cache, attention_mask, out);
    attn_final_kernel<<<dim3(NHEAD, B_), 128>>>(out);
}